// round 1
// baseline (speedup 1.0000x reference)
#include <cuda_runtime.h>
#include <cstdint>

// Problem constants
#define SIN   512          // input H=W
#define HW    128          // resized H=W and volume H=W
#define ND    128          // depth bins
#define NB    8            // batch

// Scratch: per-pixel {xray_resized, (float)d_idx}
__device__ float2 g_pix[NB * HW * HW];

// ---------------------------------------------------------------------------
// Kernel A: jax.image.resize(bilinear, antialias) 512->128 for both arrays,
// fused with d_idx computation.
// Weight structure for scale=1/4, triangle kernel, antialias:
//   taps i = 4*o - 2 + k, k=0..7, base w = {1,3,5,7,7,5,3,1}/8, renormalized
//   per-output over in-range taps (matches jax's per-dim weight matrix).
// ---------------------------------------------------------------------------
__global__ __launch_bounds__(128) void resize_kernel(
    const float* __restrict__ depth, const float* __restrict__ xray)
{
    __shared__ float2 hrow[SIN];   // H-contracted row at this output row: {d, x}

    const int ho  = blockIdx.x;    // 0..127
    const int b   = blockIdx.y;    // 0..7
    const int tid = threadIdx.x;   // 128 threads

    const float BW[8] = {0.125f, 0.375f, 0.625f, 0.875f,
                         0.875f, 0.625f, 0.375f, 0.125f};

    const int ih0 = 4 * ho - 2;

    // H weights (uniform across the block)
    float whn[8]; float hs = 0.f;
    #pragma unroll
    for (int k = 0; k < 8; k++) {
        int ih = ih0 + k;
        float w = (ih >= 0 && ih < SIN) ? BW[k] : 0.f;
        whn[k] = w; hs += w;
    }
    #pragma unroll
    for (int k = 0; k < 8; k++) whn[k] = __fdiv_rn(whn[k], hs);

    const float* dbase = depth + (size_t)b * SIN * SIN;
    const float* xbase = xray  + (size_t)b * SIN * SIN;

    // Stage 1: H contraction. Each thread owns 4 consecutive input columns
    // (coalesced float4 global loads, conflict-free SMEM stores).
    {
        const int c0 = tid * 4;
        float4 ad = make_float4(0.f, 0.f, 0.f, 0.f);
        float4 ax = make_float4(0.f, 0.f, 0.f, 0.f);
        #pragma unroll
        for (int kh = 0; kh < 8; kh++) {
            if (whn[kh] != 0.f) {
                const int ih = ih0 + kh;
                const float4 dv = *(const float4*)(dbase + (size_t)ih * SIN + c0);
                const float4 xv = *(const float4*)(xbase + (size_t)ih * SIN + c0);
                const float w = whn[kh];
                ad.x = fmaf(w, dv.x, ad.x); ad.y = fmaf(w, dv.y, ad.y);
                ad.z = fmaf(w, dv.z, ad.z); ad.w = fmaf(w, dv.w, ad.w);
                ax.x = fmaf(w, xv.x, ax.x); ax.y = fmaf(w, xv.y, ax.y);
                ax.z = fmaf(w, xv.z, ax.z); ax.w = fmaf(w, xv.w, ax.w);
            }
        }
        hrow[c0 + 0] = make_float2(ad.x, ax.x);
        hrow[c0 + 1] = make_float2(ad.y, ax.y);
        hrow[c0 + 2] = make_float2(ad.z, ax.z);
        hrow[c0 + 3] = make_float2(ad.w, ax.w);
    }
    __syncthreads();

    // Stage 2: W contraction, one output pixel per thread.
    const int wo  = tid;
    const int iw0 = 4 * wo - 2;

    float wwn[8]; float ws = 0.f;
    #pragma unroll
    for (int k = 0; k < 8; k++) {
        int iw = iw0 + k;
        float w = (iw >= 0 && iw < SIN) ? BW[k] : 0.f;
        wwn[k] = w; ws += w;
    }
    #pragma unroll
    for (int k = 0; k < 8; k++) wwn[k] = __fdiv_rn(wwn[k], ws);

    float ad = 0.f, ax = 0.f;
    #pragma unroll
    for (int k = 0; k < 8; k++) {
        if (wwn[k] != 0.f) {
            float2 p = hrow[iw0 + k];
            ad = fmaf(wwn[k], p.x, ad);
            ax = fmaf(wwn[k], p.y, ax);
        }
    }

    // d_idx = clip(int32((d/100)*127), 0, 127) — IEEE ops to match reference
    float nd = __fdiv_rn(ad, 100.0f);
    int di = (int)__fmul_rn(nd, 127.0f);   // truncation toward zero, as astype(int32)
    di = min(max(di, 0), ND - 1);

    g_pix[((size_t)b * HW + ho) * HW + wo] = make_float2(ax, (float)di);
}

// ---------------------------------------------------------------------------
// Kernel B: fused depth-splat + 3x3x3 box average.
// The depth direction of the box is folded into a 7-tap per-pixel profile:
//   profile[k] = x * sum_{j in [max(k-4,-2,-di), min(k-2,2,127-di)]} w[j]
// where w = gauss5 {e^-2, e^-.5, 1, e^-.5, e^-2}, with clipping of the
// original splat taps to [0,127] handled via the j-range.
// Then out[d,h,w] = (1/27) * sum over 3x3 (h,w) neighbors of profile(d).
//
// Block = 8h x 16w tile x full depth (128), 128 threads.
// SMEM: acc[d][col] 64KB (conflict-free: bank = tid%32), 10x18 halo profiles.
// ---------------------------------------------------------------------------
__global__ __launch_bounds__(128) void splat_pool_kernel(float* __restrict__ out)
{
    extern __shared__ float sm[];
    float* acc  = sm;                         // [128][128] = 16384 floats
    float* prof = sm + 16384;                 // [180][7]
    int*   pd0  = (int*)(sm + 16384 + 1260);  // [180]
    float* sP   = sm + 16384 + 1260 + 180;    // [6] prefix sums of gauss5

    const int tid = threadIdx.x;
    const int w0  = blockIdx.x * 16;
    const int h0  = blockIdx.y * 8;
    const int b   = blockIdx.z;

    const float E1 = 0.60653065971263342f;  // exp(-0.5)
    const float E2 = 0.13533528323661270f;  // exp(-2)

    if (tid == 0) {
        sP[0] = 0.f;
        sP[1] = E2;
        sP[2] = E2 + E1;
        sP[3] = E2 + E1 + 1.f;
        sP[4] = E2 + E1 + 1.f + E1;
        sP[5] = E2 + E1 + 1.f + E1 + E2;
    }

    // Zero the accumulator tile (float4-wide STS)
    {
        float4* a4 = (float4*)acc;
        #pragma unroll
        for (int i = tid; i < 4096; i += 128)
            a4[i] = make_float4(0.f, 0.f, 0.f, 0.f);
    }
    __syncthreads();

    // Per-pixel 7-tap profiles for the 10x18 halo tile.
    for (int n = tid; n < 180; n += 128) {
        const int ph = h0 + n / 18 - 1;
        const int pw = w0 + n % 18 - 1;
        float x = 0.f; int di = 3;
        if (ph >= 0 && ph < HW && pw >= 0 && pw < HW) {
            float2 p = g_pix[((size_t)b * HW + ph) * HW + pw];
            x = p.x; di = (int)p.y;
        }
        const int lo = max(-2, -di);
        const int hi = min(2, (ND - 1) - di);
        pd0[n] = di - 3;
        #pragma unroll
        for (int k = 0; k < 7; k++) {
            int jl = max(k - 4, lo);
            int jh = min(k - 2, hi);
            float w = (jh >= jl) ? (sP[jh + 3] - sP[jl + 2]) : 0.f;
            prof[n * 7 + k] = x * w;
        }
    }
    __syncthreads();

    // Accumulate the 9-neighbor sum into this thread's depth column.
    {
        const int ty = tid >> 4;      // 0..7  (h within tile)
        const int tx = tid & 15;      // 0..15 (w within tile)
        #pragma unroll
        for (int dh = 0; dh < 3; dh++) {
            #pragma unroll
            for (int dw = 0; dw < 3; dw++) {
                const int n  = (ty + dh) * 18 + (tx + dw);
                const int d0 = pd0[n];
                #pragma unroll
                for (int k = 0; k < 7; k++) {
                    const int d = d0 + k;
                    if (d >= 0 && d < ND)
                        acc[d * 128 + tid] += prof[n * 7 + k];
                }
            }
        }
    }
    __syncthreads();

    // Coalesced float4 writeout, /27 folded in.
    {
        const int slice = tid >> 5;        // 4 d-slices per iteration
        const int lane  = tid & 31;
        const int oy    = lane >> 2;       // 0..7
        const int og    = lane & 3;        // 0..3 (group of 4 w)
        const float inv27 = 1.0f / 27.0f;
        const size_t obase =
            (((size_t)b * ND) * HW + (h0 + oy)) * HW + w0 + og * 4;
        // note: d term added per-iteration as d*HW*HW
        #pragma unroll 4
        for (int it = 0; it < 32; it++) {
            const int d = it * 4 + slice;
            float4 v = *(float4*)&acc[d * 128 + oy * 16 + og * 4];
            v.x *= inv27; v.y *= inv27; v.z *= inv27; v.w *= inv27;
            *(float4*)&out[obase + (size_t)d * HW * HW] = v;
        }
    }
}

// ---------------------------------------------------------------------------
extern "C" void kernel_launch(void* const* d_in, const int* in_sizes, int n_in,
                              void* d_out, int out_size)
{
    const float* depth = (const float*)d_in[0];
    const float* xray  = (const float*)d_in[1];
    float* out = (float*)d_out;

    // Kernel A: resize + d_idx
    resize_kernel<<<dim3(HW, NB), 128>>>(depth, xray);

    // Kernel B: splat + 3x3x3 box average
    const int smem_b = (16384 + 180 * 7) * (int)sizeof(float)
                     + 180 * (int)sizeof(int)
                     + 6 * (int)sizeof(float);
    cudaFuncSetAttribute(splat_pool_kernel,
                         cudaFuncAttributeMaxDynamicSharedMemorySize, smem_b);
    splat_pool_kernel<<<dim3(HW / 16, HW / 8, NB), 128, smem_b>>>(out);
}

// round 2
// speedup vs baseline: 1.0082x; 1.0082x over previous
#include <cuda_runtime.h>
#include <cstdint>

// Problem constants
#define SIN   512          // input H=W
#define HW    128          // resized H=W and volume H=W
#define ND    128          // depth bins
#define NB    8            // batch

// Scratch: per-pixel {xray_resized, (float)d_idx}
__device__ float2 g_pix[NB * HW * HW];

// ---------------------------------------------------------------------------
// Kernel A: jax.image.resize(bilinear, antialias) 512->128 for both arrays,
// fused with d_idx computation. (unchanged from R1 — passes at 8e-8)
// ---------------------------------------------------------------------------
__global__ __launch_bounds__(128) void resize_kernel(
    const float* __restrict__ depth, const float* __restrict__ xray)
{
    __shared__ float2 hrow[SIN];   // H-contracted row at this output row: {d, x}

    const int ho  = blockIdx.x;    // 0..127
    const int b   = blockIdx.y;    // 0..7
    const int tid = threadIdx.x;   // 128 threads

    const float BW[8] = {0.125f, 0.375f, 0.625f, 0.875f,
                         0.875f, 0.625f, 0.375f, 0.125f};

    const int ih0 = 4 * ho - 2;

    float whn[8]; float hs = 0.f;
    #pragma unroll
    for (int k = 0; k < 8; k++) {
        int ih = ih0 + k;
        float w = (ih >= 0 && ih < SIN) ? BW[k] : 0.f;
        whn[k] = w; hs += w;
    }
    #pragma unroll
    for (int k = 0; k < 8; k++) whn[k] = __fdiv_rn(whn[k], hs);

    const float* dbase = depth + (size_t)b * SIN * SIN;
    const float* xbase = xray  + (size_t)b * SIN * SIN;

    {
        const int c0 = tid * 4;
        float4 ad = make_float4(0.f, 0.f, 0.f, 0.f);
        float4 ax = make_float4(0.f, 0.f, 0.f, 0.f);
        #pragma unroll
        for (int kh = 0; kh < 8; kh++) {
            if (whn[kh] != 0.f) {
                const int ih = ih0 + kh;
                const float4 dv = *(const float4*)(dbase + (size_t)ih * SIN + c0);
                const float4 xv = *(const float4*)(xbase + (size_t)ih * SIN + c0);
                const float w = whn[kh];
                ad.x = fmaf(w, dv.x, ad.x); ad.y = fmaf(w, dv.y, ad.y);
                ad.z = fmaf(w, dv.z, ad.z); ad.w = fmaf(w, dv.w, ad.w);
                ax.x = fmaf(w, xv.x, ax.x); ax.y = fmaf(w, xv.y, ax.y);
                ax.z = fmaf(w, xv.z, ax.z); ax.w = fmaf(w, xv.w, ax.w);
            }
        }
        hrow[c0 + 0] = make_float2(ad.x, ax.x);
        hrow[c0 + 1] = make_float2(ad.y, ax.y);
        hrow[c0 + 2] = make_float2(ad.z, ax.z);
        hrow[c0 + 3] = make_float2(ad.w, ax.w);
    }
    __syncthreads();

    const int wo  = tid;
    const int iw0 = 4 * wo - 2;

    float wwn[8]; float ws = 0.f;
    #pragma unroll
    for (int k = 0; k < 8; k++) {
        int iw = iw0 + k;
        float w = (iw >= 0 && iw < SIN) ? BW[k] : 0.f;
        wwn[k] = w; ws += w;
    }
    #pragma unroll
    for (int k = 0; k < 8; k++) wwn[k] = __fdiv_rn(wwn[k], ws);

    float ad = 0.f, ax = 0.f;
    #pragma unroll
    for (int k = 0; k < 8; k++) {
        if (wwn[k] != 0.f) {
            float2 p = hrow[iw0 + k];
            ad = fmaf(wwn[k], p.x, ad);
            ax = fmaf(wwn[k], p.y, ax);
        }
    }

    // d_idx = clip(int32((d/100)*127), 0, 127) — IEEE ops to match reference
    float nd = __fdiv_rn(ad, 100.0f);
    int di = (int)__fmul_rn(nd, 127.0f);
    di = min(max(di, 0), ND - 1);

    g_pix[((size_t)b * HW + ho) * HW + wo] = make_float2(ax, (float)di);
}

// ---------------------------------------------------------------------------
// Kernel B: fused depth-splat + 3x3x3 box average.
//   out[b,d,h,w] = sum over 3x3 (h,w) nbhd of prof[n][d - pd0[n]]
// prof = (x/27) * box3-of-clipped-gauss5, a 7-tap profile per pixel.
//
// R2 change: 256 threads/block, depth-PARITY split — two threads per column,
// thread parity p handles only taps with (d&1)==p. Halves per-thread serial
// work in every phase and doubles warps/SM at the same 64KB acc footprint.
// ---------------------------------------------------------------------------
__global__ __launch_bounds__(256) void splat_pool_kernel(float* __restrict__ out)
{
    extern __shared__ float sm[];
    float* acc  = sm;                         // [128][128] = 16384 floats
    float* prof = sm + 16384;                 // [180][7]  (weights include /27)
    int*   pd0  = (int*)(sm + 16384 + 1260);  // [180]
    float* sP   = sm + 16384 + 1260 + 180;    // [6] prefix sums of gauss5/27

    const int tid = threadIdx.x;              // 0..255
    const int p   = tid >> 7;                 // depth parity this thread owns
    const int ct  = tid & 127;                // column within 8x16 tile
    const int w0  = blockIdx.x * 16;
    const int h0  = blockIdx.y * 8;
    const int b   = blockIdx.z;

    const float inv27 = 1.0f / 27.0f;
    const float E1 = 0.60653065971263342f * inv27;  // exp(-0.5)/27
    const float E2 = 0.13533528323661270f * inv27;  // exp(-2)/27
    const float E0 = inv27;

    if (tid == 0) {
        sP[0] = 0.f;
        sP[1] = E2;
        sP[2] = E2 + E1;
        sP[3] = E2 + E1 + E0;
        sP[4] = E2 + E1 + E0 + E1;
        sP[5] = E2 + E1 + E0 + E1 + E2;
    }

    // Zero the accumulator tile (float4 STS, 16 per thread)
    {
        float4* a4 = (float4*)acc;
        #pragma unroll
        for (int i = tid; i < 4096; i += 256)
            a4[i] = make_float4(0.f, 0.f, 0.f, 0.f);
    }
    __syncthreads();

    // Per-pixel 7-tap profiles for the 10x18 halo tile (one pixel per thread).
    if (tid < 180) {
        const int n  = tid;
        const int ph = h0 + n / 18 - 1;
        const int pw = w0 + n % 18 - 1;
        float x = 0.f; int di = 3;
        if (ph >= 0 && ph < HW && pw >= 0 && pw < HW) {
            float2 q = g_pix[((size_t)b * HW + ph) * HW + pw];
            x = q.x; di = (int)q.y;
        }
        const int lo = max(-2, -di);
        const int hi = min(2, (ND - 1) - di);
        pd0[n] = di - 3;
        #pragma unroll
        for (int k = 0; k < 7; k++) {
            int jl = max(k - 4, lo);
            int jh = min(k - 2, hi);
            float w = (jh >= jl) ? (sP[jh + 3] - sP[jl + 2]) : 0.f;
            prof[n * 7 + k] = x * w;
        }
    }
    __syncthreads();

    // Accumulate the 9-neighbor sum into this thread's (column, parity) set.
    {
        const int ty = ct >> 4;       // 0..7  (h within tile)
        const int tx = ct & 15;       // 0..15 (w within tile)
        #pragma unroll
        for (int dh = 0; dh < 3; dh++) {
            #pragma unroll
            for (int dw = 0; dw < 3; dw++) {
                const int n  = (ty + dh) * 18 + (tx + dw);
                const int d0 = pd0[n];
                const int ks = (p ^ (d0 & 1)) & 1;   // first tap of my parity
                #pragma unroll
                for (int kk = 0; kk < 4; kk++) {
                    const int k = ks + 2 * kk;
                    const int d = d0 + k;
                    if (k < 7 && d >= 0 && d < ND)
                        acc[d * 128 + ct] += prof[n * 7 + k];
                }
            }
        }
    }
    __syncthreads();

    // Coalesced float4 writeout (/27 already folded into prof).
    {
        #pragma unroll
        for (int it = 0; it < 16; it++) {
            const int i    = tid + 256 * it;     // float4 index in acc
            const int d    = i >> 5;             // 32 float4 per d-slice
            const int col4 = (i & 31) * 4;       // column of first float
            const int oy   = col4 >> 4;          // 0..7
            const int ox   = col4 & 15;          // 0,4,8,12
            float4 v = *(float4*)&acc[d * 128 + col4];
            *(float4*)&out[(((size_t)b * ND + d) * HW + (h0 + oy)) * HW + w0 + ox] = v;
        }
    }
}

// ---------------------------------------------------------------------------
extern "C" void kernel_launch(void* const* d_in, const int* in_sizes, int n_in,
                              void* d_out, int out_size)
{
    const float* depth = (const float*)d_in[0];
    const float* xray  = (const float*)d_in[1];
    float* out = (float*)d_out;

    // Kernel A: resize + d_idx
    resize_kernel<<<dim3(HW, NB), 128>>>(depth, xray);

    // Kernel B: splat + 3x3x3 box average
    const int smem_b = (16384 + 180 * 7) * (int)sizeof(float)
                     + 180 * (int)sizeof(int)
                     + 6 * (int)sizeof(float);
    cudaFuncSetAttribute(splat_pool_kernel,
                         cudaFuncAttributeMaxDynamicSharedMemorySize, smem_b);
    splat_pool_kernel<<<dim3(HW / 16, HW / 8, NB), 256, smem_b>>>(out);
}